// round 1
// baseline (speedup 1.0000x reference)
#include <cuda_runtime.h>

// Problem shape (fixed by the reference setup_inputs)
#define BB 8
#define CC 64
#define HH 256
#define WW 448
#define HW (HH * WW)          // 114688
#define NPIX (BB * HW)        // 917504

__global__ __launch_bounds__(256)
void warp_bilinear_kernel(const float* __restrict__ img,   // [B,C,H,W]
                          const float* __restrict__ flow,  // [B,2,H,W]
                          float* __restrict__ out)         // [B,C,H,W]
{
    int idx = blockIdx.x * blockDim.x + threadIdx.x;
    if (idx >= NPIX) return;

    int b   = idx / HW;
    int rem = idx - b * HW;       // h*W + w
    int h   = rem / WW;
    int w   = rem - h * WW;

    // flow: dx at [b,0,h,w], dy at [b,1,h,w]
    const float fx = flow[b * 2 * HW + rem];
    const float fy = flow[b * 2 * HW + HW + rem];

    const float x = (float)w + fx;
    const float y = (float)h + fy;

    const float x0f = floorf(x);
    const float y0f = floorf(y);
    const int x0 = (int)x0f;
    const int y0 = (int)y0f;
    const int x1 = x0 + 1;
    const int y1 = y0 + 1;

    const float wx1 = x - x0f;
    const float wx0 = 1.0f - wx1;
    const float wy1 = y - y0f;
    const float wy0 = 1.0f - wy1;

    const bool vx0 = (x0 >= 0) & (x0 <= WW - 1);
    const bool vx1 = (x1 >= 0) & (x1 <= WW - 1);
    const bool vy0 = (y0 >= 0) & (y0 <= HH - 1);
    const bool vy1 = (y1 >= 0) & (y1 <= HH - 1);

    // zero the weight of any OOB tap; loads use clamped (safe) addresses
    const float w00 = (vy0 & vx0) ? wy0 * wx0 : 0.0f;
    const float w01 = (vy0 & vx1) ? wy0 * wx1 : 0.0f;
    const float w10 = (vy1 & vx0) ? wy1 * wx0 : 0.0f;
    const float w11 = (vy1 & vx1) ? wy1 * wx1 : 0.0f;

    const int xc0 = min(max(x0, 0), WW - 1);
    const int xc1 = min(max(x1, 0), WW - 1);
    const int yc0 = min(max(y0, 0), HH - 1);
    const int yc1 = min(max(y1, 0), HH - 1);

    const int o00 = yc0 * WW + xc0;
    const int o01 = yc0 * WW + xc1;
    const int o10 = yc1 * WW + xc0;
    const int o11 = yc1 * WW + xc1;

    const float* __restrict__ src = img + (size_t)b * CC * HW;
    float* __restrict__ dst       = out + (size_t)b * CC * HW + rem;

    // Channel loop: stores coalesced (consecutive threads -> consecutive w),
    // taps near-coalesced (flow magnitude ~4 px). Unroll 8 -> 32 LDGs in
    // flight per thread to hide DRAM latency.
    #pragma unroll 8
    for (int c = 0; c < CC; c++) {
        const float* __restrict__ p = src + c * HW;
        float v = w00 * __ldg(p + o00)
                + w01 * __ldg(p + o01)
                + w10 * __ldg(p + o10)
                + w11 * __ldg(p + o11);
        dst[c * HW] = v;
    }
}

extern "C" void kernel_launch(void* const* d_in, const int* in_sizes, int n_in,
                              void* d_out, int out_size)
{
    const float* input1 = (const float*)d_in[0];  // [8,64,256,448] fp32
    const float* input2 = (const float*)d_in[1];  // [8,2,256,448] fp32
    float* out = (float*)d_out;

    const int threads = 256;
    const int blocks = (NPIX + threads - 1) / threads;
    warp_bilinear_kernel<<<blocks, threads>>>(input1, input2, out);
}

// round 2
// speedup vs baseline: 1.5278x; 1.5278x over previous
#include <cuda_runtime.h>

// Problem shape (fixed by the reference setup_inputs)
#define BB 8
#define CC 64
#define HH 256
#define WW 448
#define HW (HH * WW)            // 114688
#define CHW (CC * HW)           // 7340032
#define NPIX (BB * HW)          // 917504

// 28 MB scratch for one batch of NHWC-transposed input. Reused for every
// batch (sequential kernel launches in one stream) so it stays L2-resident
// and its dirty lines are overwritten before writeback.
__device__ float g_nhwc[HW * CC];

// ---------------------------------------------------------------------------
// Pass 1: NCHW -> NHWC transpose for one batch.
// in:  [CC][HW] (row-major), out: g_nhwc [HW][CC].
// Classic 32x32 smem tile, 32x8 threads, coalesced 128B on both sides.
// ---------------------------------------------------------------------------
__global__ __launch_bounds__(256)
void transpose_kernel(const float* __restrict__ in)  // in = input1 + b*CHW
{
    __shared__ float tile[32][33];

    const int p0 = blockIdx.x * 32;   // pixel tile base (HW dim)
    const int c0 = blockIdx.y * 32;   // channel tile base
    const int tx = threadIdx.x;       // 0..31
    const int ty = threadIdx.y;       // 0..7

    #pragma unroll
    for (int i = 0; i < 4; i++) {
        tile[ty + 8 * i][tx] = in[(size_t)(c0 + ty + 8 * i) * HW + p0 + tx];
    }
    __syncthreads();
    #pragma unroll
    for (int i = 0; i < 4; i++) {
        g_nhwc[(size_t)(p0 + ty + 8 * i) * CC + c0 + tx] = tile[tx][ty + 8 * i];
    }
}

// ---------------------------------------------------------------------------
// Pass 2: bilinear warp for one batch, reading NHWC scratch.
// 256 threads = 16 pixels x 16 threads; each thread owns 4 channels (float4).
// Each tap load: 16 lanes x 16B = 256B fully-dense contiguous -> minimal L1
// wavefronts independent of flow divergence. Output staged via smem so the
// NCHW stores are coalesced.
// ---------------------------------------------------------------------------
__global__ __launch_bounds__(256)
void warp_gather_kernel(const float* __restrict__ flow,  // flow + b*2*HW
                        float* __restrict__ out)         // out + b*CHW
{
    __shared__ float sm[16][68];   // [pixel][channel], padded (68*4 % 16 == 0)

    const int tid = threadIdx.x;
    const int pxl = tid >> 4;      // 0..15 : pixel within block
    const int t   = tid & 15;      // 0..15 : channel quad

    const int p = blockIdx.x * 16 + pxl;     // pixel index in [0, HW)
    const int h = p / WW;
    const int w = p - h * WW;

    // flow loads: 16 lanes hit the same address -> broadcast, 1 sector each
    const float fx = __ldg(flow + p);
    const float fy = __ldg(flow + HW + p);

    const float x = (float)w + fx;
    const float y = (float)h + fy;

    const float x0f = floorf(x);
    const float y0f = floorf(y);
    const int x0 = (int)x0f;
    const int y0 = (int)y0f;
    const int x1 = x0 + 1;
    const int y1 = y0 + 1;

    const float wx1 = x - x0f;
    const float wx0 = 1.0f - wx1;
    const float wy1 = y - y0f;
    const float wy0 = 1.0f - wy1;

    const bool vx0 = (x0 >= 0) & (x0 <= WW - 1);
    const bool vx1 = (x1 >= 0) & (x1 <= WW - 1);
    const bool vy0 = (y0 >= 0) & (y0 <= HH - 1);
    const bool vy1 = (y1 >= 0) & (y1 <= HH - 1);

    const float w00 = (vy0 & vx0) ? wy0 * wx0 : 0.0f;
    const float w01 = (vy0 & vx1) ? wy0 * wx1 : 0.0f;
    const float w10 = (vy1 & vx0) ? wy1 * wx0 : 0.0f;
    const float w11 = (vy1 & vx1) ? wy1 * wx1 : 0.0f;

    const int xc0 = min(max(x0, 0), WW - 1);
    const int xc1 = min(max(x1, 0), WW - 1);
    const int yc0 = min(max(y0, 0), HH - 1);
    const int yc1 = min(max(y1, 0), HH - 1);

    // tap base addresses as float4 indices into NHWC scratch
    const float4* __restrict__ s = (const float4*)g_nhwc;
    const int o00 = (yc0 * WW + xc0) * 16 + t;   // 16 float4 per pixel
    const int o01 = (yc0 * WW + xc1) * 16 + t;
    const int o10 = (yc1 * WW + xc0) * 16 + t;
    const int o11 = (yc1 * WW + xc1) * 16 + t;

    const float4 v00 = __ldg(s + o00);
    const float4 v01 = __ldg(s + o01);
    const float4 v10 = __ldg(s + o10);
    const float4 v11 = __ldg(s + o11);

    float4 acc;
    acc.x = w00 * v00.x + w01 * v01.x + w10 * v10.x + w11 * v11.x;
    acc.y = w00 * v00.y + w01 * v01.y + w10 * v10.y + w11 * v11.y;
    acc.z = w00 * v00.z + w01 * v01.z + w10 * v10.z + w11 * v11.z;
    acc.w = w00 * v00.w + w01 * v01.w + w10 * v10.w + w11 * v11.w;

    *(float4*)&sm[pxl][4 * t] = acc;
    __syncthreads();

    // store NCHW: 64 channels x 16 pixels = 1024 floats, 4 iters of 256.
    // consecutive tid -> consecutive pixel within a channel -> 64B segments.
    const int p_base = blockIdx.x * 16;
    #pragma unroll
    for (int k = 0; k < 4; k++) {
        const int idx = tid + 256 * k;
        const int c = idx >> 4;
        const int j = idx & 15;
        out[(size_t)c * HW + p_base + j] = sm[j][c];
    }
}

extern "C" void kernel_launch(void* const* d_in, const int* in_sizes, int n_in,
                              void* d_out, int out_size)
{
    const float* input1 = (const float*)d_in[0];  // [8,64,256,448] fp32
    const float* input2 = (const float*)d_in[1];  // [8,2,256,448] fp32
    float* out = (float*)d_out;

    dim3 tgrid(HW / 32, CC / 32);   // 3584 x 2
    dim3 tblock(32, 8);
    const int wgrid = HW / 16;      // 7168
    const int wblock = 256;

    // Interleave per batch so the 28MB NHWC scratch stays L2-resident
    // between its producer (transpose) and consumer (gather).
    for (int b = 0; b < BB; b++) {
        transpose_kernel<<<tgrid, tblock>>>(input1 + (size_t)b * CHW);
        warp_gather_kernel<<<wgrid, wblock>>>(input2 + (size_t)b * 2 * HW,
                                              out + (size_t)b * CHW);
    }
}